// round 5
// baseline (speedup 1.0000x reference)
#include <cuda_runtime.h>

#define SEQ   8192
#define DIM   2048
#define H     16
#define DH    128
#define PDIM  512
#define EPSF  1e-5f
#define NCH3  64
#define CH3   (SEQ / NCH3)        // 128 rows per k3 chunk
#define K1_BLOCKS 128
#define K1_ROWS   64
#define LSCALE 0.08838834764831845f   // 1/sqrt(128)

typedef unsigned long long ull;

// ---------------- scratch (device globals) ----------------------------------
__device__ __align__(16) ull   g_Wqp[DIM * 8];            // [j][hp] packed head-pairs
__device__ __align__(16) float g_attn[H * SEQ];           // UNNORMALIZED exp weights
__device__ __align__(16) float g_psum[K1_BLOCKS * H];     // per-block per-head exp sums
__device__ __align__(16) float g_ypart[NCH3][H * DIM];    // partial y sums
__device__ __align__(16) float g_y[H * DIM];              // normalized y
__device__ __align__(16) float g_x1[DIM];
__device__ __align__(16) float g_h1[PDIM];
__device__ __align__(16) float g_add[DIM];

// ---------------- packed f32x2 helpers ---------------------------------------
__device__ __forceinline__ ull splat2(float a) {
    ull r; asm("mov.b64 %0, {%1, %1};" : "=l"(r) : "f"(a)); return r;
}
__device__ __forceinline__ ull pack2(float lo, float hi) {
    ull r; asm("mov.b64 %0, {%1, %2};" : "=l"(r) : "f"(lo), "f"(hi)); return r;
}
__device__ __forceinline__ void unpack2(ull v, float& lo, float& hi) {
    asm("mov.b64 {%0, %1}, %2;" : "=f"(lo), "=f"(hi) : "l"(v));
}
__device__ __forceinline__ void ffma2(ull& d, ull a, ull b) {
    asm("fma.rn.f32x2 %0, %1, %2, %0;" : "+l"(d) : "l"(a), "l"(b));
}

// ---- dummy kernels: position k1 as 4th launch for ncu capture ---------------
__global__ void knop1() {}
__global__ void knop2() {}

// ---- k0: Wqp[j][hp] = pack( q_h . W_k[h,:,j] for h=2hp, 2hp+1 ) -------------
__global__ void k0_wq(const float* __restrict__ q,
                      const float* __restrict__ Wkv) {
    int idx = blockIdx.x * 256 + threadIdx.x;    // 16384 threads
    int hp = idx >> 11, j = idx & (DIM - 1);
    int h0 = 2 * hp, h1 = 2 * hp + 1;
    const float* w0 = Wkv + (size_t)h0 * DH * DIM + j;
    const float* w1 = Wkv + (size_t)h1 * DH * DIM + j;
    const float* q0 = q + h0 * DH;
    const float* q1 = q + h1 * DH;
    float a0 = 0.f, a1 = 0.f;
    #pragma unroll 8
    for (int d = 0; d < DH; ++d) {
        a0 += q0[d] * w0[(size_t)d * DIM];
        a1 += q1[d] * w1[(size_t)d * DIM];
    }
    g_Wqp[(size_t)j * 8 + hp] = pack2(a0, a1);
}

// ---- k1: exp-logits + per-block head sums -----------------------------------
__global__ void __launch_bounds__(256) k1_logits(const float* __restrict__ x) {
    extern __shared__ __align__(16) unsigned char smem[];
    ull*   wq_s = (ull*)smem;                         // [2048][8]
    float* xsb  = (float*)(smem + 131072);            // 8 x [64][18]
    float* part = (float*)(smem + 167936);            // 8 x [64][20]
    __shared__ float wsum[8][16];

    int tid = threadIdx.x, lane = tid & 31, wid = tid >> 5;
    int rowbase = blockIdx.x * K1_ROWS;

    {
        const float4* src = (const float4*)g_Wqp;     // 8192 float4
        float4* dst = (float4*)wq_s;
        for (int i = tid; i < 8192; i += 256) dst[i] = src[i];
    }
    __syncthreads();

    float* xw = xsb + wid * (64 * 18);
    ull accA[8], accB[8];
    #pragma unroll
    for (int hp = 0; hp < 8; ++hp) { accA[hp] = 0ull; accB[hp] = 0ull; }
    int jslice = wid * 256;

    for (int ch = 0; ch < 16; ++ch) {
        int j0 = jslice + ch * 16;
        #pragma unroll
        for (int t = 0; t < 8; ++t) {
            int id = t * 32 + lane;
            int r = id >> 2, c4 = id & 3;
            float4 v = *(const float4*)(x + (size_t)(rowbase + r) * DIM + j0 + c4 * 4);
            float* p = xw + r * 18 + c4 * 4;
            p[0] = v.x; p[1] = v.y; p[2] = v.z; p[3] = v.w;
        }
        __syncwarp();
        #pragma unroll
        for (int jp = 0; jp < 8; ++jp) {
            int j = j0 + jp * 2;
            const ulonglong2* wp = (const ulonglong2*)(wq_s + (size_t)j * 8);
            ulonglong2 a0 = wp[0], a1 = wp[1], a2 = wp[2], a3 = wp[3];  // j
            ulonglong2 b0 = wp[4], b1 = wp[5], b2 = wp[6], b3 = wp[7];  // j+1
            ull w0[8] = {a0.x, a0.y, a1.x, a1.y, a2.x, a2.y, a3.x, a3.y};
            ull w1[8] = {b0.x, b0.y, b1.x, b1.y, b2.x, b2.y, b3.x, b3.y};
            float2 xa = *(const float2*)(xw + lane * 18 + jp * 2);
            float2 xb = *(const float2*)(xw + (lane + 32) * 18 + jp * 2);
            ull sax = splat2(xa.x), say = splat2(xa.y);
            ull sbx = splat2(xb.x), sby = splat2(xb.y);
            #pragma unroll
            for (int hp = 0; hp < 8; ++hp) {
                ffma2(accA[hp], sax, w0[hp]);
                ffma2(accA[hp], say, w1[hp]);
                ffma2(accB[hp], sbx, w0[hp]);
                ffma2(accB[hp], sby, w1[hp]);
            }
        }
        __syncwarp();
    }

    float* pw = part + wid * (64 * 20);
    {
        float fa[16], fb[16];
        #pragma unroll
        for (int hp = 0; hp < 8; ++hp) {
            unpack2(accA[hp], fa[2 * hp], fa[2 * hp + 1]);
            unpack2(accB[hp], fb[2 * hp], fb[2 * hp + 1]);
        }
        #pragma unroll
        for (int k = 0; k < 4; ++k) {
            *(float4*)(pw + lane * 20 + 4 * k) =
                make_float4(fa[4 * k], fa[4 * k + 1], fa[4 * k + 2], fa[4 * k + 3]);
            *(float4*)(pw + (lane + 32) * 20 + 4 * k) =
                make_float4(fb[4 * k], fb[4 * k + 1], fb[4 * k + 2], fb[4 * k + 3]);
        }
    }
    __syncthreads();

    int h = tid & 15, g = tid >> 4;                   // 16 heads x 16 row-groups
    float hsum = 0.f, ev[4];
    #pragma unroll
    for (int k = 0; k < 4; ++k) {
        int r = g * 4 + k;
        float s = 0.f;
        #pragma unroll
        for (int w = 0; w < 8; ++w) s += part[w * 1280 + r * 20 + h];
        float e = __expf(s * LSCALE);
        ev[k] = e; hsum += e;
    }
    *(float4*)(g_attn + (size_t)h * SEQ + rowbase + g * 4) =
        make_float4(ev[0], ev[1], ev[2], ev[3]);
    hsum += __shfl_xor_sync(0xffffffffu, hsum, 16);
    if (lane < 16) wsum[wid][h] = hsum;
    __syncthreads();
    if (tid < 16) {
        float s = 0.f;
        #pragma unroll
        for (int w = 0; w < 8; ++w) s += wsum[w][tid];
        g_psum[blockIdx.x * 16 + tid] = s;
    }
}

// ---- k3: partial y over s-chunk; 2 cols x 8 head-pair f32x2 accs ------------
__global__ void __launch_bounds__(256) k3_yaccum(const float* __restrict__ x) {
    int c = blockIdx.x >> 2;               // 64 chunks
    int qq = blockIdx.x & 3;               // col quarter
    int tid = threadIdx.x;
    int col0 = qq * 512 + 2 * tid;
    __shared__ ull sat2[CH3 * 8];          // 8 KB, packed attn head-pairs
    int s0 = c * CH3;
    for (int i = tid; i < CH3 * 8; i += 256) {
        int sl = i >> 3, hp = i & 7;
        sat2[i] = pack2(g_attn[(size_t)(2 * hp) * SEQ + s0 + sl],
                        g_attn[(size_t)(2 * hp + 1) * SEQ + s0 + sl]);
    }
    __syncthreads();
    ull aa[8], ab[8];
    #pragma unroll
    for (int hp = 0; hp < 8; ++hp) { aa[hp] = 0ull; ab[hp] = 0ull; }
    for (int sl = 0; sl < CH3; ++sl) {
        float2 xv = *(const float2*)(x + (size_t)(s0 + sl) * DIM + col0);
        ull sa = splat2(xv.x), sb = splat2(xv.y);
        const ulonglong2* sp = (const ulonglong2*)(sat2 + sl * 8);
        ulonglong2 p0 = sp[0], p1 = sp[1], p2 = sp[2], p3 = sp[3];
        ffma2(aa[0], sa, p0.x); ffma2(ab[0], sb, p0.x);
        ffma2(aa[1], sa, p0.y); ffma2(ab[1], sb, p0.y);
        ffma2(aa[2], sa, p1.x); ffma2(ab[2], sb, p1.x);
        ffma2(aa[3], sa, p1.y); ffma2(ab[3], sb, p1.y);
        ffma2(aa[4], sa, p2.x); ffma2(ab[4], sb, p2.x);
        ffma2(aa[5], sa, p2.y); ffma2(ab[5], sb, p2.y);
        ffma2(aa[6], sa, p3.x); ffma2(ab[6], sb, p3.x);
        ffma2(aa[7], sa, p3.y); ffma2(ab[7], sb, p3.y);
    }
    float* yp = g_ypart[c];
    #pragma unroll
    for (int hp = 0; hp < 8; ++hp) {
        float l0, h0, l1, h1;
        unpack2(aa[hp], l0, h0);
        unpack2(ab[hp], l1, h1);
        *(float2*)(yp + (size_t)(2 * hp) * DIM + col0)     = make_float2(l0, l1);
        *(float2*)(yp + (size_t)(2 * hp + 1) * DIM + col0) = make_float2(h0, h1);
    }
}

// ---- k3b: reduce partials (float4, unrolled), normalize -> g_y --------------
__global__ void __launch_bounds__(256) k3b_reduce() {
    __shared__ float partr[16][16];
    __shared__ float inv[16];
    int tid = threadIdx.x;
    {   // reduce g_psum[128][16] deterministically
        int h = tid & 15, g = tid >> 4;
        float s = 0.f;
        #pragma unroll
        for (int b = 0; b < 8; ++b) s += g_psum[(g * 8 + b) * 16 + h];
        partr[g][h] = s;
    }
    __syncthreads();
    if (tid < 16) {
        float s = 0.f;
        #pragma unroll
        for (int g = 0; g < 16; ++g) s += partr[g][tid];
        inv[tid] = 1.f / s;
    }
    __syncthreads();
    int i = blockIdx.x * 256 + tid;          // float4 index, 8192 total
    float4 s = make_float4(0.f, 0.f, 0.f, 0.f);
    const float4* base = (const float4*)&g_ypart[0][0];
    #pragma unroll 8
    for (int c = 0; c < NCH3; ++c) {
        float4 v = base[(size_t)c * (H * DIM / 4) + i];
        s.x += v.x; s.y += v.y; s.z += v.z; s.w += v.w;
    }
    float iv = inv[(i >> 9) & 15];           // float-idx = 4i; head = (4i>>11)&15
    s.x *= iv; s.y *= iv; s.z *= iv; s.w *= iv;
    ((float4*)g_y)[i] = s;
}

// ---- k4: x1[i] = W_v[i,:] . y[h(i),:] + b_v[i] ------------------------------
__global__ void __launch_bounds__(256) k4_x1(const float* __restrict__ Wkv,
                                             const float* __restrict__ bkv) {
    int warp = (blockIdx.x * 256 + threadIdx.x) >> 5;  // 2048 warps
    int lane = threadIdx.x & 31;
    int h = warp >> 7;
    const float4* w = (const float4*)(Wkv + (size_t)(DIM + warp) * DIM);
    const float4* y = (const float4*)(g_y + (size_t)h * DIM);
    float a = 0.f;
    for (int it = lane; it < DIM / 4; it += 32) {
        float4 wv = w[it], yv = y[it];
        a += wv.x * yv.x + wv.y * yv.y + wv.z * yv.z + wv.w * yv.w;
    }
    #pragma unroll
    for (int o = 16; o > 0; o >>= 1) a += __shfl_xor_sync(0xffffffffu, a, o);
    if (lane == 0) g_x1[warp] = a + bkv[DIM + warp];
}

// ---- k5: h1 = W_p1 @ x1 + b_p1 ----------------------------------------------
__global__ void __launch_bounds__(256) k5_p1(const float* __restrict__ Wp1,
                                             const float* __restrict__ bp1) {
    int warp = (blockIdx.x * 256 + threadIdx.x) >> 5;  // 512 warps
    int lane = threadIdx.x & 31;
    const float4* w = (const float4*)(Wp1 + (size_t)warp * DIM);
    const float4* v = (const float4*)g_x1;
    float a = 0.f;
    for (int it = lane; it < DIM / 4; it += 32) {
        float4 wv = w[it], vv = v[it];
        a += wv.x * vv.x + wv.y * vv.y + wv.z * vv.z + wv.w * vv.w;
    }
    #pragma unroll
    for (int o = 16; o > 0; o >>= 1) a += __shfl_xor_sync(0xffffffffu, a, o);
    if (lane == 0) g_h1[warp] = a + bp1[warp];
}

// ---- k67: LN(h1)+relu (redundant per block) then add = W_p2 @ r + b_p2 ------
__global__ void __launch_bounds__(256) k67_lnp2(const float* __restrict__ Wp2,
                                                const float* __restrict__ bp2,
                                                const float* __restrict__ lnw,
                                                const float* __restrict__ lnb) {
    __shared__ __align__(16) float r_s[PDIM];
    __shared__ float red[256];
    int tid = threadIdx.x;
    float2 v2 = *(const float2*)(g_h1 + tid * 2);
    red[tid] = v2.x + v2.y; __syncthreads();
    for (int o = 128; o > 0; o >>= 1) {
        if (tid < o) red[tid] += red[tid + o];
        __syncthreads();
    }
    float mu = red[0] * (1.f / PDIM);
    __syncthreads();
    float dx = v2.x - mu, dy = v2.y - mu;
    red[tid] = dx * dx + dy * dy; __syncthreads();
    for (int o = 128; o > 0; o >>= 1) {
        if (tid < o) red[tid] += red[tid + o];
        __syncthreads();
    }
    float rstd = rsqrtf(red[0] * (1.f / PDIM) + EPSF);
    float2 w2 = *(const float2*)(lnw + tid * 2);
    float2 b2 = *(const float2*)(lnb + tid * 2);
    r_s[2 * tid]     = fmaxf(dx * rstd * w2.x + b2.x, 0.f);
    r_s[2 * tid + 1] = fmaxf(dy * rstd * w2.y + b2.y, 0.f);
    __syncthreads();
    int wid = tid >> 5, lane = tid & 31;
    #pragma unroll
    for (int k = 0; k < 4; ++k) {
        int row = blockIdx.x * 32 + wid * 4 + k;
        const float4* w = (const float4*)(Wp2 + (size_t)row * PDIM);
        float a = 0.f;
        #pragma unroll
        for (int it = lane; it < PDIM / 4; it += 32) {
            float4 wv = w[it];
            float4 rv = *(const float4*)(r_s + it * 4);
            a += wv.x * rv.x + wv.y * rv.y + wv.z * rv.z + wv.w * rv.w;
        }
        #pragma unroll
        for (int o = 16; o > 0; o >>= 1) a += __shfl_xor_sync(0xffffffffu, a, o);
        if (lane == 0) g_add[row] = a + bp2[row];
    }
}

// ---- k8: out = x + broadcast(add); grid-stride, 16 indep loads/thread -------
#define K8_BLOCKS 1024
__global__ void __launch_bounds__(256) k8_resid(const float* __restrict__ x,
                                                float* __restrict__ out) {
    int i0 = blockIdx.x * 256 + threadIdx.x;          // float4 index base
    const float4* x4 = (const float4*)x;
    float4* o4 = (float4*)out;
    // stride = 262144 float4 = multiple of 512 -> add-vector index invariant
    float4 av = ((const float4*)g_add)[i0 & (DIM / 4 - 1)];
    #pragma unroll 16
    for (int k = 0; k < 16; ++k) {
        size_t i = (size_t)i0 + (size_t)k * (K8_BLOCKS * 256);
        float4 xv = __ldcs(x4 + i);
        float4 o;
        o.x = xv.x + av.x; o.y = xv.y + av.y;
        o.z = xv.z + av.z; o.w = xv.w + av.w;
        __stcs(o4 + i, o);
    }
}

extern "C" void kernel_launch(void* const* d_in, const int* in_sizes, int n_in,
                              void* d_out, int out_size) {
    const float* x    = (const float*)d_in[0];
    const float* q    = (const float*)d_in[1];
    const float* Wkv  = (const float*)d_in[2];
    const float* bkv  = (const float*)d_in[3];
    const float* Wp1  = (const float*)d_in[4];
    const float* bp1  = (const float*)d_in[5];
    const float* Wp2  = (const float*)d_in[6];
    const float* bp2  = (const float*)d_in[7];
    const float* lnw  = (const float*)d_in[8];
    const float* lnb  = (const float*)d_in[9];
    float* out = (float*)d_out;

    static bool attr_set = false;
    if (!attr_set) {
        cudaFuncSetAttribute(k1_logits,
                             cudaFuncAttributeMaxDynamicSharedMemorySize, 208896);
        attr_set = true;
    }

    k0_wq<<<64, 256>>>(q, Wkv);
    knop1<<<1, 32>>>();
    knop2<<<1, 32>>>();
    k1_logits<<<K1_BLOCKS, 256, 208896>>>(x);   // 4th launch -> ncu capture
    k3_yaccum<<<NCH3 * 4, 256>>>(x);
    k3b_reduce<<<32, 256>>>();
    k4_x1<<<DIM / 8, 256>>>(Wkv, bkv);
    k5_p1<<<PDIM / 8, 256>>>(Wp1, bp1);
    k67_lnp2<<<DIM / 32, 256>>>(Wp2, bp2, lnw, lnb);
    k8_resid<<<K8_BLOCKS, 256>>>(x, out);
}

// round 7
// speedup vs baseline: 1.0786x; 1.0786x over previous
#include <cuda_runtime.h>

#define SEQ   8192
#define DIM   2048
#define H     16
#define DH    128
#define PDIM  512
#define EPSF  1e-5f
#define NCH3  128
#define CH3   (SEQ / NCH3)            // 64 rows per k3 chunk
#define LSCALE 0.08838834764831845f   // 1/sqrt(128)

typedef unsigned long long ull;

// ---------------- scratch (device globals) ----------------------------------
__device__ __align__(16) float g_Wqf[DIM * H];            // [j][h] folded key proj
__device__ __align__(16) float g_lp[4 * H * SEQ];         // raw logit quarter-sums
__device__ __align__(16) float g_attn[H * SEQ];           // UNNORMALIZED exp weights
__device__ __align__(16) float g_psum[32 * H];            // per-block head exp sums
__device__ __align__(16) float g_ypart[NCH3][H * DIM];    // partial y sums (16MB)
__device__ __align__(16) float g_y[H * DIM];              // normalized y
__device__ __align__(16) float g_x1[DIM];
__device__ __align__(16) float g_h1[PDIM];
__device__ __align__(16) float g_add[DIM];

// ---------------- packed f32x2 helpers ---------------------------------------
__device__ __forceinline__ ull splat2(float a) {
    ull r; asm("mov.b64 %0, {%1, %1};" : "=l"(r) : "f"(a)); return r;
}
__device__ __forceinline__ ull pack2(float lo, float hi) {
    ull r; asm("mov.b64 %0, {%1, %2};" : "=l"(r) : "f"(lo), "f"(hi)); return r;
}
__device__ __forceinline__ void unpack2(ull v, float& lo, float& hi) {
    asm("mov.b64 {%0, %1}, %2;" : "=f"(lo), "=f"(hi) : "l"(v));
}
__device__ __forceinline__ void ffma2(ull& d, ull a, ull b) {
    asm("fma.rn.f32x2 %0, %1, %2, %0;" : "+l"(d) : "l"(a), "l"(b));
}

// ---- k0: Wqf[j][h] = q_h . W_k[h-block, :, j] -------------------------------
__global__ void __launch_bounds__(256) k0_wq(const float* __restrict__ q,
                                             const float* __restrict__ Wkv) {
    int idx = blockIdx.x * 256 + threadIdx.x;   // 32768 threads: one per (h,j)
    int h = idx >> 11, j = idx & (DIM - 1);
    const float* w  = Wkv + (size_t)h * DH * DIM + j;   // coalesced across lanes
    const float* qh = q + h * DH;
    float a = 0.f;
    #pragma unroll 8
    for (int d = 0; d < DH; ++d)
        a += qh[d] * w[(size_t)d * DIM];
    g_Wqf[j * H + h] = a;
}

// ---- k1: raw partial logits per (128-row chunk, 512-j quarter) --------------
// 8 warps x 64-j slices; thread owns rows lane+{0,32,64,96}; weights broadcast
// from smem; x staged per-warp. Epilogue: per-row 16-head sums -> g_lp.
// smem: Wq quarter 32KB | x stage 8 x [128][18] floats = 72KB  (partials alias)
#define K1_SMEM (32768 + 8 * 128 * 18 * 4)
__global__ void __launch_bounds__(256, 2) k1_logits(const float* __restrict__ x) {
    extern __shared__ __align__(16) unsigned char smem[];
    ull*   wq_s = (ull*)smem;                       // [512][8]
    float* xsb  = (float*)(smem + 32768);           // 8 x [128][18]

    int tid = threadIdx.x, lane = tid & 31, wid = tid >> 5;
    int jq = blockIdx.x & 3, rc = blockIdx.x >> 2;
    int rowbase = rc * 128, jbase = jq * 512;

    {   // stage Wq quarter: 4096 ull = 2048 float4
        const float4* src = (const float4*)(g_Wqf + (size_t)jbase * H);
        float4* dst = (float4*)wq_s;
        #pragma unroll
        for (int i = tid; i < 2048; i += 256) dst[i] = src[i];
    }
    __syncthreads();

    float* xw = xsb + wid * (128 * 18);
    ull acc[4][8];
    #pragma unroll
    for (int k = 0; k < 4; ++k)
        #pragma unroll
        for (int hp = 0; hp < 8; ++hp) acc[k][hp] = 0ull;

    #pragma unroll
    for (int ch = 0; ch < 4; ++ch) {                // 16-j chunks within 64-j slice
        int j0 = jbase + wid * 64 + ch * 16;        // global j
        #pragma unroll
        for (int t = 0; t < 16; ++t) {              // stage 128 rows x 16 j
            int id = t * 32 + lane;
            int r = id >> 2, c4 = id & 3;
            float4 v = *(const float4*)(x + (size_t)(rowbase + r) * DIM + j0 + c4 * 4);
            float* p = xw + r * 18 + c4 * 4;
            p[0] = v.x; p[1] = v.y; p[2] = v.z; p[3] = v.w;
        }
        __syncwarp();
        #pragma unroll
        for (int jp = 0; jp < 8; ++jp) {
            int jl = wid * 64 + ch * 16 + jp * 2;   // local j within quarter
            const ulonglong2* wp = (const ulonglong2*)(wq_s + (size_t)jl * 8);
            ulonglong2 a0 = wp[0], a1 = wp[1], a2 = wp[2], a3 = wp[3];  // j
            ulonglong2 b0 = wp[4], b1 = wp[5], b2 = wp[6], b3 = wp[7];  // j+1
            ull w0[8] = {a0.x, a0.y, a1.x, a1.y, a2.x, a2.y, a3.x, a3.y};
            ull w1[8] = {b0.x, b0.y, b1.x, b1.y, b2.x, b2.y, b3.x, b3.y};
            #pragma unroll
            for (int k = 0; k < 4; ++k) {
                float2 xv = *(const float2*)(xw + (lane + 32 * k) * 18 + jp * 2);
                ull sx = splat2(xv.x), sy = splat2(xv.y);
                #pragma unroll
                for (int hp = 0; hp < 8; ++hp) {
                    ffma2(acc[k][hp], sx, w0[hp]);
                    ffma2(acc[k][hp], sy, w1[hp]);
                }
            }
        }
        __syncwarp();
    }

    // write per-warp partials [r][16] (stride 16) into own region
    float* pw = xsb + wid * (128 * 18);             // reuse, stride 16 inside
    #pragma unroll
    for (int k = 0; k < 4; ++k) {
        float f[16];
        #pragma unroll
        for (int hp = 0; hp < 8; ++hp) unpack2(acc[k][hp], f[2 * hp], f[2 * hp + 1]);
        int r = lane + 32 * k;
        #pragma unroll
        for (int m = 0; m < 4; ++m)
            *(float4*)(pw + r * 16 + 4 * m) =
                make_float4(f[4 * m], f[4 * m + 1], f[4 * m + 2], f[4 * m + 3]);
    }
    __syncthreads();

    // combine 8 warps -> raw logit quarter-sums
    int h = tid & 15, g = tid >> 4;                 // 16 heads x 16 row-groups of 8
    float ev[8];
    #pragma unroll
    for (int ri = 0; ri < 8; ++ri) {
        int r = g * 8 + ri;
        float s = 0.f;
        #pragma unroll
        for (int w = 0; w < 8; ++w) s += xsb[w * (128 * 18) + r * 16 + h];
        ev[ri] = s;
    }
    float* dst = g_lp + (size_t)(jq * H + h) * SEQ + rowbase + g * 8;
    *(float4*)(dst)     = make_float4(ev[0], ev[1], ev[2], ev[3]);
    *(float4*)(dst + 4) = make_float4(ev[4], ev[5], ev[6], ev[7]);
}

// ---- k2c: combine quarters + exp + per-block head sums ----------------------
__global__ void __launch_bounds__(256) k2c_exp() {
    __shared__ float wred[8][16];
    int tid = threadIdx.x, lane = tid & 31, wid = tid >> 5;
    int s = blockIdx.x * 256 + tid;                 // 32 blocks
    float hsum[16];
    #pragma unroll
    for (int h = 0; h < 16; ++h) {
        float v = g_lp[(size_t)(0 * H + h) * SEQ + s]
                + g_lp[(size_t)(1 * H + h) * SEQ + s]
                + g_lp[(size_t)(2 * H + h) * SEQ + s]
                + g_lp[(size_t)(3 * H + h) * SEQ + s];
        float e = __expf(v * LSCALE);
        g_attn[(size_t)h * SEQ + s] = e;
        hsum[h] = e;
    }
    #pragma unroll
    for (int h = 0; h < 16; ++h)
        #pragma unroll
        for (int o = 16; o > 0; o >>= 1)
            hsum[h] += __shfl_xor_sync(0xffffffffu, hsum[h], o);
    if (lane == 0)
        #pragma unroll
        for (int h = 0; h < 16; ++h) wred[wid][h] = hsum[h];
    __syncthreads();
    if (tid < 16) {
        float t = 0.f;
        #pragma unroll
        for (int w = 0; w < 8; ++w) t += wred[w][tid];
        g_psum[blockIdx.x * 16 + tid] = t;
    }
}

// ---- k3: partial y over 64-row chunk; thread owns 4 cols, 16 heads ----------
__global__ void __launch_bounds__(256) k3_yaccum(const float* __restrict__ x) {
    int c = blockIdx.x >> 1;               // 128 chunks
    int half = blockIdx.x & 1;
    int tid = threadIdx.x;
    int col0 = half * 1024 + tid * 4;
    __shared__ ull sat2[CH3 * 8];          // 4 KB packed attn head-pairs
    int s0 = c * CH3;
    for (int i = tid; i < CH3 * 8; i += 256) {
        int sl = i >> 3, hp = i & 7;
        sat2[i] = pack2(g_attn[(size_t)(2 * hp) * SEQ + s0 + sl],
                        g_attn[(size_t)(2 * hp + 1) * SEQ + s0 + sl]);
    }
    __syncthreads();
    ull acc[4][8];
    #pragma unroll
    for (int cc = 0; cc < 4; ++cc)
        #pragma unroll
        for (int hp = 0; hp < 8; ++hp) acc[cc][hp] = 0ull;
    #pragma unroll 4
    for (int sl = 0; sl < CH3; ++sl) {
        float4 xv = *(const float4*)(x + (size_t)(s0 + sl) * DIM + col0);
        ull sx = splat2(xv.x), sy = splat2(xv.y), sz = splat2(xv.z), sw = splat2(xv.w);
        const ulonglong2* sp = (const ulonglong2*)(sat2 + sl * 8);
        ulonglong2 p0 = sp[0], p1 = sp[1], p2 = sp[2], p3 = sp[3];
        ull w[8] = {p0.x, p0.y, p1.x, p1.y, p2.x, p2.y, p3.x, p3.y};
        #pragma unroll
        for (int hp = 0; hp < 8; ++hp) {
            ffma2(acc[0][hp], sx, w[hp]);
            ffma2(acc[1][hp], sy, w[hp]);
            ffma2(acc[2][hp], sz, w[hp]);
            ffma2(acc[3][hp], sw, w[hp]);
        }
    }
    float* yp = g_ypart[c];
    #pragma unroll
    for (int hp = 0; hp < 8; ++hp) {
        float l0, h0, l1, h1, l2, h2, l3, h3;
        unpack2(acc[0][hp], l0, h0);
        unpack2(acc[1][hp], l1, h1);
        unpack2(acc[2][hp], l2, h2);
        unpack2(acc[3][hp], l3, h3);
        *(float4*)(yp + (size_t)(2 * hp) * DIM + col0)     = make_float4(l0, l1, l2, l3);
        *(float4*)(yp + (size_t)(2 * hp + 1) * DIM + col0) = make_float4(h0, h1, h2, h3);
    }
}

// ---- k3b: reduce partials, normalize -> g_y ---------------------------------
__global__ void __launch_bounds__(256) k3b_reduce() {
    __shared__ float inv[16];
    int tid = threadIdx.x;
    if (tid < 16) {
        float s = 0.f;
        #pragma unroll
        for (int b = 0; b < 32; ++b) s += g_psum[b * 16 + tid];
        inv[tid] = 1.f / s;
    }
    __syncthreads();
    int i = blockIdx.x * 256 + tid;          // float4 index, 8192 total (32 blocks)
    float4 s = make_float4(0.f, 0.f, 0.f, 0.f);
    const float4* base = (const float4*)&g_ypart[0][0];
    #pragma unroll 8
    for (int c = 0; c < NCH3; ++c) {
        float4 v = base[(size_t)c * (H * DIM / 4) + i];
        s.x += v.x; s.y += v.y; s.z += v.z; s.w += v.w;
    }
    float iv = inv[(i >> 9) & 15];
    s.x *= iv; s.y *= iv; s.z *= iv; s.w *= iv;
    ((float4*)g_y)[i] = s;
}

// ---- k4: x1[i] = W_v[i,:] . y[h(i),:] + b_v[i] ------------------------------
__global__ void __launch_bounds__(256) k4_x1(const float* __restrict__ Wkv,
                                             const float* __restrict__ bkv) {
    int warp = (blockIdx.x * 256 + threadIdx.x) >> 5;  // 2048 warps
    int lane = threadIdx.x & 31;
    int h = warp >> 7;
    const float4* w = (const float4*)(Wkv + (size_t)(DIM + warp) * DIM);
    const float4* y = (const float4*)(g_y + (size_t)h * DIM);
    float a = 0.f;
    for (int it = lane; it < DIM / 4; it += 32) {
        float4 wv = w[it], yv = y[it];
        a += wv.x * yv.x + wv.y * yv.y + wv.z * yv.z + wv.w * yv.w;
    }
    #pragma unroll
    for (int o = 16; o > 0; o >>= 1) a += __shfl_xor_sync(0xffffffffu, a, o);
    if (lane == 0) g_x1[warp] = a + bkv[DIM + warp];
}

// ---- k5: h1 = W_p1 @ x1 + b_p1 ----------------------------------------------
__global__ void __launch_bounds__(256) k5_p1(const float* __restrict__ Wp1,
                                             const float* __restrict__ bp1) {
    int warp = (blockIdx.x * 256 + threadIdx.x) >> 5;  // 512 warps
    int lane = threadIdx.x & 31;
    const float4* w = (const float4*)(Wp1 + (size_t)warp * DIM);
    const float4* v = (const float4*)g_x1;
    float a = 0.f;
    for (int it = lane; it < DIM / 4; it += 32) {
        float4 wv = w[it], vv = v[it];
        a += wv.x * vv.x + wv.y * vv.y + wv.z * vv.z + wv.w * vv.w;
    }
    #pragma unroll
    for (int o = 16; o > 0; o >>= 1) a += __shfl_xor_sync(0xffffffffu, a, o);
    if (lane == 0) g_h1[warp] = a + bp1[warp];
}

// ---- k67: LN(h1)+relu (redundant per block) then add = W_p2 @ r + b_p2 ------
__global__ void __launch_bounds__(256) k67_lnp2(const float* __restrict__ Wp2,
                                                const float* __restrict__ bp2,
                                                const float* __restrict__ lnw,
                                                const float* __restrict__ lnb) {
    __shared__ __align__(16) float r_s[PDIM];
    __shared__ float red[256];
    int tid = threadIdx.x;
    float2 v2 = *(const float2*)(g_h1 + tid * 2);
    red[tid] = v2.x + v2.y; __syncthreads();
    for (int o = 128; o > 0; o >>= 1) {
        if (tid < o) red[tid] += red[tid + o];
        __syncthreads();
    }
    float mu = red[0] * (1.f / PDIM);
    __syncthreads();
    float dx = v2.x - mu, dy = v2.y - mu;
    red[tid] = dx * dx + dy * dy; __syncthreads();
    for (int o = 128; o > 0; o >>= 1) {
        if (tid < o) red[tid] += red[tid + o];
        __syncthreads();
    }
    float rstd = rsqrtf(red[0] * (1.f / PDIM) + EPSF);
    float2 w2 = *(const float2*)(lnw + tid * 2);
    float2 b2 = *(const float2*)(lnb + tid * 2);
    r_s[2 * tid]     = fmaxf(dx * rstd * w2.x + b2.x, 0.f);
    r_s[2 * tid + 1] = fmaxf(dy * rstd * w2.y + b2.y, 0.f);
    __syncthreads();
    int wid = tid >> 5, lane = tid & 31;
    #pragma unroll
    for (int k = 0; k < 4; ++k) {
        int row = blockIdx.x * 32 + wid * 4 + k;
        const float4* w = (const float4*)(Wp2 + (size_t)row * PDIM);
        float a = 0.f;
        #pragma unroll
        for (int it = lane; it < PDIM / 4; it += 32) {
            float4 wv = w[it];
            float4 rv = *(const float4*)(r_s + it * 4);
            a += wv.x * rv.x + wv.y * rv.y + wv.z * rv.z + wv.w * rv.w;
        }
        #pragma unroll
        for (int o = 16; o > 0; o >>= 1) a += __shfl_xor_sync(0xffffffffu, a, o);
        if (lane == 0) g_add[row] = a + bp2[row];
    }
}

// ---- k8: out = x + broadcast(add); contiguous tiles, MLP 4 ------------------
__global__ void __launch_bounds__(256) k8_resid(const float* __restrict__ x,
                                                float* __restrict__ out) {
    int tid = threadIdx.x;
    size_t tile = (size_t)blockIdx.x * 1024;          // float4 units
    const float4* x4 = (const float4*)x;
    float4* o4 = (float4*)out;
    const float4* a4 = (const float4*)g_add;
    float4 av0 = a4[tid];                              // (tile%512==0)
    float4 av1 = a4[tid + 256];
    #pragma unroll
    for (int k = 0; k < 4; ++k) {
        size_t i = tile + (size_t)k * 256 + tid;
        float4 xv = x4[i];
        float4 av = (k & 1) ? av1 : av0;
        float4 o;
        o.x = xv.x + av.x; o.y = xv.y + av.y;
        o.z = xv.z + av.z; o.w = xv.w + av.w;
        o4[i] = o;
    }
}

extern "C" void kernel_launch(void* const* d_in, const int* in_sizes, int n_in,
                              void* d_out, int out_size) {
    const float* x    = (const float*)d_in[0];
    const float* q    = (const float*)d_in[1];
    const float* Wkv  = (const float*)d_in[2];
    const float* bkv  = (const float*)d_in[3];
    const float* Wp1  = (const float*)d_in[4];
    const float* bp1  = (const float*)d_in[5];
    const float* Wp2  = (const float*)d_in[6];
    const float* bp2  = (const float*)d_in[7];
    const float* lnw  = (const float*)d_in[8];
    const float* lnb  = (const float*)d_in[9];
    float* out = (float*)d_out;

    static bool attr_set = false;
    if (!attr_set) {
        cudaFuncSetAttribute(k1_logits,
                             cudaFuncAttributeMaxDynamicSharedMemorySize, K1_SMEM);
        attr_set = true;
    }

    k0_wq<<<128, 256>>>(q, Wkv);
    k1_logits<<<256, 256, K1_SMEM>>>(x);
    k2c_exp<<<32, 256>>>();
    k3_yaccum<<<NCH3 * 2, 256>>>(x);       // 4th launch -> ncu capture
    k3b_reduce<<<32, 256>>>();
    k4_x1<<<DIM / 8, 256>>>(Wkv, bkv);
    k5_p1<<<PDIM / 8, 256>>>(Wp1, bp1);
    k67_lnp2<<<DIM / 32, 256>>>(Wp2, bp2, lnw, lnb);
    k8_resid<<<SEQ * DIM / 4096, 256>>>(x, out);
}